// round 1
// baseline (speedup 1.0000x reference)
#include <cuda_runtime.h>
#include <cuda_bf16.h>
#include <cstddef>

// ManyBodyVoxel: out[b=0, a, c=t*2+l, x, y, z] =
//   sum_n exp(coeff * || grid_l[x,y,z] - d[a,n]*mask_t[a,n] ||^2)
// Separable Gaussian: per-(atom,axis,tick) exp tables + rank-1 outer products.
// Non-matching atoms contribute the d=0 base Gaussian (mask zeroes d, doesn't drop the term).

#define NTHREADS 256

__global__ __launch_bounds__(NTHREADS, 2)
void mbv_kernel(const float* __restrict__ dist,     // (1,128,64,3)
                const float* __restrict__ sigma,    // (1,)
                const int*   __restrict__ anum_raw, // (128,64) int32 or int64 (auto-detect)
                float* __restrict__ out)            // (1,128,10,16,16,16)
{
    const int a = blockIdx.x >> 1;   // atom-row 0..127
    const int l = blockIdx.x & 1;    // grid length 0:8.0, 1:12.0
    const float L = l ? 12.0f : 8.0f;
    const int tid = threadIdx.x;

    __shared__ __align__(16) float tab[65][3][16]; // atom 64 = base (d=0)
    __shared__ int lst[5][64];
    __shared__ int cnt[5];
    __shared__ int is64;

    if (tid < 5) cnt[tid] = 0;
    if (tid == 0) is64 = 1;
    __syncthreads();
    // Detect int64 vs int32: int64 small values => every odd 32-bit word of the
    // first 64 entries is 0. False-positive prob for int32 ~ (1/17)^64 ~ 0.
    if (tid < 64 && anum_raw[2 * tid + 1] != 0) atomicAnd(&is64, 0);
    __syncthreads();
    const int w64 = is64;

    if (tid < 64) {
        int z = w64 ? anum_raw[(a * 64 + tid) * 2] : anum_raw[a * 64 + tid];
        int t = (z == 1) ? 0 : (z == 6) ? 1 : (z == 7) ? 2 : (z == 8) ? 3 : (z == 16) ? 4 : -1;
        if (t >= 0) {
            int idx = atomicAdd(&cnt[t], 1);
            lst[t][idx] = tid;
        }
    }

    const float s    = sigma[0];
    const float cf   = -0.5f / (s * s);
    const float half = 0.5f * L;
    const float step = L * (1.0f / 15.0f);

    // Exp tables: 65 atoms x 3 axes x 16 ticks = 3120 exps, ~12/thread.
    for (int i = tid; i < 65 * 48; i += NTHREADS) {
        int n  = i / 48;
        int r  = i - n * 48;
        int ax = r >> 4;
        int j  = r & 15;
        float dv = (n < 64) ? dist[(a * 64 + n) * 3 + ax] : 0.0f;
        float u  = (step * (float)j - half) - dv;
        tab[n][ax][j] = __expf(cf * u * u);
    }
    __syncthreads();

    const int x = tid >> 4;
    const int y = tid & 15;

    #pragma unroll
    for (int t = 0; t < 5; t++) {
        float4 a0 = make_float4(0.f, 0.f, 0.f, 0.f);
        float4 a1 = a0, a2 = a0, a3 = a0;
        const int c = cnt[t];
        for (int k = 0; k < c; k++) {
            int n = lst[t][k];
            float sxy = tab[n][0][x] * tab[n][1][y];
            const float4* ez = reinterpret_cast<const float4*>(tab[n][2]);
            float4 e0 = ez[0], e1 = ez[1], e2 = ez[2], e3 = ez[3];
            a0.x += sxy * e0.x; a0.y += sxy * e0.y; a0.z += sxy * e0.z; a0.w += sxy * e0.w;
            a1.x += sxy * e1.x; a1.y += sxy * e1.y; a1.z += sxy * e1.z; a1.w += sxy * e1.w;
            a2.x += sxy * e2.x; a2.y += sxy * e2.y; a2.z += sxy * e2.z; a2.w += sxy * e2.w;
            a3.x += sxy * e3.x; a3.y += sxy * e3.y; a3.z += sxy * e3.z; a3.w += sxy * e3.w;
        }
        // Base contribution from the (64 - c) non-matching atoms (d = 0).
        float bm = (float)(64 - c) * tab[64][0][x] * tab[64][1][y];
        const float4* bz = reinterpret_cast<const float4*>(tab[64][2]);
        float4 b0 = bz[0], b1 = bz[1], b2 = bz[2], b3 = bz[3];
        a0.x += bm * b0.x; a0.y += bm * b0.y; a0.z += bm * b0.z; a0.w += bm * b0.w;
        a1.x += bm * b1.x; a1.y += bm * b1.y; a1.z += bm * b1.z; a1.w += bm * b1.w;
        a2.x += bm * b2.x; a2.y += bm * b2.y; a2.z += bm * b2.z; a2.w += bm * b2.w;
        a3.x += bm * b3.x; a3.y += bm * b3.y; a3.z += bm * b3.z; a3.w += bm * b3.w;

        // Channel c = t*2 + l; voxel index = x*256 + y*16 + z.
        size_t off = (((size_t)(a * 10 + t * 2 + l)) << 12) + ((size_t)x << 8) + ((size_t)y << 4);
        float4* op = reinterpret_cast<float4*>(out + off);
        op[0] = a0; op[1] = a1; op[2] = a2; op[3] = a3;
    }
}

extern "C" void kernel_launch(void* const* d_in, const int* in_sizes, int n_in,
                              void* d_out, int out_size) {
    const float* dist = nullptr;
    const float* sig  = nullptr;
    const int*   an   = nullptr;
    for (int i = 0; i < n_in; i++) {
        if (in_sizes[i] == 1)          sig  = (const float*)d_in[i];
        else if (in_sizes[i] == 24576) dist = (const float*)d_in[i];
        else if (in_sizes[i] == 8192)  an   = (const int*)d_in[i];
    }
    // Fallback to declaration order if sizes ever change.
    if (!dist) dist = (const float*)d_in[0];
    if (!sig)  sig  = (const float*)d_in[1];
    if (!an)   an   = (const int*)d_in[2];

    mbv_kernel<<<256, NTHREADS>>>(dist, sig, an, (float*)d_out);
}